// round 1
// baseline (speedup 1.0000x reference)
#include <cuda_runtime.h>
#include <cuda_bf16.h>
#include <math.h>

// Problem constants
#define BATCH 8
#define SEQ   1024
#define DMODEL 1024
#define NHEAD 16
#define HDIM  64
#define KVD   2048   // 2*DMODEL

// ---------------- scratch (no cudaMalloc allowed) ----------------
__device__ float g_q[BATCH * SEQ * DMODEL];      // 32 MB
__device__ float g_kv[BATCH * SEQ * KVD];        // 64 MB
__device__ float g_heads[BATCH * SEQ * DMODEL];  // 32 MB

// ---------------- SGEMM: C[M,N] = A[M,K] @ B[K,N] + bias[N] ----------------
#define BM 128
#define BN 128
#define BK 8
#define TM 8
#define TN 8

__global__ __launch_bounds__(256, 2) void sgemm_bias(
    const float* __restrict__ A, const float* __restrict__ B,
    const float* __restrict__ bias, float* __restrict__ C,
    int M, int N, int K)
{
    __shared__ float As[BK][BM];   // A stored k-major (transposed on load)
    __shared__ float Bs[BK][BN];

    const int tid = threadIdx.x;
    const int tx = tid & 15;         // 16 thread cols
    const int ty = tid >> 4;         // 16 thread rows
    const int brow = blockIdx.y;
    const int bcol = blockIdx.x;

    const float* Ag = A + (size_t)brow * BM * K;
    const float* Bg = B + (size_t)bcol * BN;

    // A tile: 128 rows x 8 cols -> 256 threads x 1 float4
    const int aRow = tid >> 1;
    const int aCol = (tid & 1) * 4;
    // B tile: 8 rows x 128 cols -> 256 threads x 1 float4
    const int bRow = tid >> 5;
    const int bCol = (tid & 31) * 4;

    float acc[TM][TN];
    #pragma unroll
    for (int i = 0; i < TM; i++)
        #pragma unroll
        for (int j = 0; j < TN; j++) acc[i][j] = 0.0f;

    for (int k0 = 0; k0 < K; k0 += BK) {
        float4 a4 = *(const float4*)(Ag + (size_t)aRow * K + k0 + aCol);
        As[aCol + 0][aRow] = a4.x;
        As[aCol + 1][aRow] = a4.y;
        As[aCol + 2][aRow] = a4.z;
        As[aCol + 3][aRow] = a4.w;
        *(float4*)(&Bs[bRow][bCol]) =
            *(const float4*)(Bg + (size_t)(k0 + bRow) * N + bCol);
        __syncthreads();

        #pragma unroll
        for (int kk = 0; kk < BK; kk++) {
            float ar[TM], br[TN];
            *(float4*)&ar[0] = *(float4*)&As[kk][ty * TM];
            *(float4*)&ar[4] = *(float4*)&As[kk][ty * TM + 4];
            *(float4*)&br[0] = *(float4*)&Bs[kk][tx * TN];
            *(float4*)&br[4] = *(float4*)&Bs[kk][tx * TN + 4];
            #pragma unroll
            for (int i = 0; i < TM; i++)
                #pragma unroll
                for (int j = 0; j < TN; j++)
                    acc[i][j] = fmaf(ar[i], br[j], acc[i][j]);
        }
        __syncthreads();
    }

    // epilogue: + bias, write
    #pragma unroll
    for (int i = 0; i < TM; i++) {
        const size_t row = (size_t)brow * BM + ty * TM + i;
        #pragma unroll
        for (int j = 0; j < TN; j += 4) {
            const int col = bcol * BN + tx * TN + j;
            float4 o;
            o.x = acc[i][j + 0] + bias[col + 0];
            o.y = acc[i][j + 1] + bias[col + 1];
            o.z = acc[i][j + 2] + bias[col + 2];
            o.w = acc[i][j + 3] + bias[col + 3];
            *(float4*)(C + row * N + col) = o;
        }
    }
}

// ---------------- Flash attention ----------------
// grid: (S/64, H, B), block: 256 (16x16), each thread owns 4x4 of the
// 64(q-rows) x 64(cols) tiles. Online softmax; no S x S materialization.
#define AQ 64      // q rows per CTA
#define AK 64      // keys per iteration
#define SMS 68     // smem row stride (floats), 16B-aligned rows
#define ATTN_SMEM (4 * 64 * SMS * 4)   // Qs,Kst,Vs,Ps = 69632 B

__global__ __launch_bounds__(256) void attn_kernel(
    const float* __restrict__ q, const float* __restrict__ kv,
    float* __restrict__ heads)
{
    const int qb = blockIdx.x;   // q tile
    const int h  = blockIdx.y;
    const int b  = blockIdx.z;
    const int tid = threadIdx.x;
    const int tx = tid & 15;
    const int ty = tid >> 4;

    extern __shared__ float sm[];
    float* Qs  = sm;                 // [64][SMS]  q-row major
    float* Kst = Qs  + 64 * SMS;     // [64][SMS]  DIM-major: Kst[kd][key]
    float* Vs  = Kst + 64 * SMS;     // [64][SMS]  key-major: Vs[key][vd]
    float* Ps  = Vs  + 64 * SMS;     // [64][SMS]  q-row major probs

    const float scale = 0.125f;      // 1/sqrt(64)

    // Load Q tile (64 x 64), coalesced float4
    const float* qg = q + ((size_t)b * SEQ + (size_t)qb * AQ) * DMODEL + h * HDIM;
    for (int i = tid; i < AQ * 16; i += 256) {
        const int r = i >> 4, c4 = (i & 15) * 4;
        *(float4*)&Qs[r * SMS + c4] = *(const float4*)(qg + (size_t)r * DMODEL + c4);
    }

    const float* kg = kv + (size_t)b * SEQ * KVD + h * HDIM;
    const float* vg = kg + DMODEL;

    float m[4], l[4], acc[4][4];
    #pragma unroll
    for (int i = 0; i < 4; i++) {
        m[i] = -INFINITY; l[i] = 0.0f;
        #pragma unroll
        for (int j = 0; j < 4; j++) acc[i][j] = 0.0f;
    }

    for (int k0 = 0; k0 < SEQ; k0 += AK) {
        // Load K tile transposed (dim-major) and V tile (key-major)
        for (int i = tid; i < AK * 16; i += 256) {
            const int kr = i >> 4, c4 = (i & 15) * 4;
            float4 kvv = *(const float4*)(kg + (size_t)(k0 + kr) * KVD + c4);
            Kst[(c4 + 0) * SMS + kr] = kvv.x;
            Kst[(c4 + 1) * SMS + kr] = kvv.y;
            Kst[(c4 + 2) * SMS + kr] = kvv.z;
            Kst[(c4 + 3) * SMS + kr] = kvv.w;
            *(float4*)&Vs[kr * SMS + c4] =
                *(const float4*)(vg + (size_t)(k0 + kr) * KVD + c4);
        }
        __syncthreads();

        // S tile = Qs @ K^T (rows ty*4.., cols tx*4..)
        float s[4][4];
        #pragma unroll
        for (int i = 0; i < 4; i++)
            #pragma unroll
            for (int j = 0; j < 4; j++) s[i][j] = 0.0f;

        #pragma unroll 8
        for (int kd = 0; kd < HDIM; kd++) {
            const float4 kc = *(const float4*)&Kst[kd * SMS + tx * 4];
            #pragma unroll
            for (int i = 0; i < 4; i++) {
                const float qv = Qs[(ty * 4 + i) * SMS + kd];
                s[i][0] = fmaf(qv, kc.x, s[i][0]);
                s[i][1] = fmaf(qv, kc.y, s[i][1]);
                s[i][2] = fmaf(qv, kc.z, s[i][2]);
                s[i][3] = fmaf(qv, kc.w, s[i][3]);
            }
        }

        // Online softmax. The 16 threads sharing q-row group ty are one
        // half-warp -> shfl_xor(1,2,4,8) reduces across the full row.
        float alpha[4];
        #pragma unroll
        for (int i = 0; i < 4; i++) {
            float pm = fmaxf(fmaxf(s[i][0], s[i][1]), fmaxf(s[i][2], s[i][3])) * scale;
            #pragma unroll
            for (int o = 1; o < 16; o <<= 1)
                pm = fmaxf(pm, __shfl_xor_sync(0xffffffffu, pm, o));
            const float nm = fmaxf(m[i], pm);
            alpha[i] = __expf(m[i] - nm);
            m[i] = nm;
            float ps = 0.0f;
            #pragma unroll
            for (int j = 0; j < 4; j++) {
                s[i][j] = __expf(fmaf(s[i][j], scale, -nm));
                ps += s[i][j];
            }
            #pragma unroll
            for (int o = 1; o < 16; o <<= 1)
                ps += __shfl_xor_sync(0xffffffffu, ps, o);
            l[i] = l[i] * alpha[i] + ps;
            #pragma unroll
            for (int j = 0; j < 4; j++) acc[i][j] *= alpha[i];
        }

        // Stash P to smem for the PV product
        #pragma unroll
        for (int i = 0; i < 4; i++)
            *(float4*)&Ps[(ty * 4 + i) * SMS + tx * 4] =
                make_float4(s[i][0], s[i][1], s[i][2], s[i][3]);
        __syncthreads();

        // acc += P @ V
        #pragma unroll 8
        for (int kr = 0; kr < AK; kr++) {
            const float4 vv = *(const float4*)&Vs[kr * SMS + tx * 4];
            #pragma unroll
            for (int i = 0; i < 4; i++) {
                const float pv = Ps[(ty * 4 + i) * SMS + kr];
                acc[i][0] = fmaf(pv, vv.x, acc[i][0]);
                acc[i][1] = fmaf(pv, vv.y, acc[i][1]);
                acc[i][2] = fmaf(pv, vv.z, acc[i][2]);
                acc[i][3] = fmaf(pv, vv.w, acc[i][3]);
            }
        }
        __syncthreads();   // before next iter overwrites Kst/Vs/Ps
    }

    // Normalize and write head output
    float* og = heads + ((size_t)b * SEQ + (size_t)qb * AQ) * DMODEL + h * HDIM;
    #pragma unroll
    for (int i = 0; i < 4; i++) {
        const int r = ty * 4 + i;
        const float inv = 1.0f / l[i];
        *(float4*)(og + (size_t)r * DMODEL + tx * 4) =
            make_float4(acc[i][0] * inv, acc[i][1] * inv,
                        acc[i][2] * inv, acc[i][3] * inv);
    }
}

// ---------------- launch ----------------
extern "C" void kernel_launch(void* const* d_in, const int* in_sizes, int n_in,
                              void* d_out, int out_size)
{
    const float* query = (const float*)d_in[0];
    const float* value = (const float*)d_in[1];
    const float* Wq    = (const float*)d_in[2];
    const float* bq    = (const float*)d_in[3];
    const float* Wkv   = (const float*)d_in[4];
    const float* bkv   = (const float*)d_in[5];
    const float* Wo    = (const float*)d_in[6];
    const float* bo    = (const float*)d_in[7];
    float* out = (float*)d_out;

    float *gq, *gkv, *gheads;
    cudaGetSymbolAddress((void**)&gq, g_q);
    cudaGetSymbolAddress((void**)&gkv, g_kv);
    cudaGetSymbolAddress((void**)&gheads, g_heads);

    const int M = BATCH * SEQ;   // 8192

    // q = query @ Wq + bq
    sgemm_bias<<<dim3(DMODEL / BN, M / BM), 256>>>(query, Wq, bq, gq,
                                                   M, DMODEL, DMODEL);
    // kv = value @ Wkv + bkv
    sgemm_bias<<<dim3(KVD / BN, M / BM), 256>>>(value, Wkv, bkv, gkv,
                                                M, KVD, DMODEL);
    // attention
    cudaFuncSetAttribute(attn_kernel, cudaFuncAttributeMaxDynamicSharedMemorySize,
                         ATTN_SMEM);
    attn_kernel<<<dim3(SEQ / AQ, NHEAD, BATCH), 256, ATTN_SMEM>>>(gq, gkv, gheads);
    // out = heads @ Wo + bo
    sgemm_bias<<<dim3(DMODEL / BN, M / BM), 256>>>(gheads, Wo, bo, out,
                                                   M, DMODEL, DMODEL);
}

// round 4
// speedup vs baseline: 2.8937x; 2.8937x over previous
#include <cuda_runtime.h>
#include <cuda_bf16.h>
#include <math.h>
#include <stdint.h>

// Problem constants
#define BATCH 8
#define SEQ   1024
#define DMODEL 1024
#define NHEAD 16
#define HDIM  64
#define KVD   2048   // 2*DMODEL

// ---------------- scratch (no cudaMalloc allowed) ----------------
__device__ float g_q[BATCH * SEQ * DMODEL];      // 32 MB
__device__ float g_kv[BATCH * SEQ * KVD];        // 64 MB
__device__ float g_heads[BATCH * SEQ * DMODEL];  // 32 MB
__device__ float g_WqT[DMODEL * DMODEL];         // 4 MB
__device__ float g_WkvT[KVD * DMODEL];           // 8 MB
__device__ float g_WoT[DMODEL * DMODEL];         // 4 MB

// ================= helpers =================
__device__ __forceinline__ uint32_t smem_u32(const void* p) {
    uint32_t a;
    asm("{ .reg .u64 t; cvta.to.shared.u64 t, %1; cvt.u32.u64 %0, t; }"
        : "=r"(a) : "l"(p));
    return a;
}

__device__ __forceinline__ void cp_async16(uint32_t dst, const void* src) {
    asm volatile("cp.async.cg.shared.global [%0], [%1], 16;"
                 :: "r"(dst), "l"(src) : "memory");
}
#define CP_COMMIT() asm volatile("cp.async.commit_group;" ::: "memory")
#define CP_WAIT(n)  asm volatile("cp.async.wait_group %0;" :: "n"(n) : "memory")

__device__ __forceinline__ uint32_t f2tf32(float x) {
    uint32_t r;
    asm("cvt.rna.tf32.f32 %0, %1;" : "=r"(r) : "f"(x));
    return r;
}

// D = A(row) @ B(col) + C, tf32, m16n8k8
__device__ __forceinline__ void mma_tf32(float* c, const uint32_t* a,
                                         const uint32_t* b) {
    asm volatile(
        "mma.sync.aligned.m16n8k8.row.col.f32.tf32.tf32.f32 "
        "{%0,%1,%2,%3}, {%4,%5,%6,%7}, {%8,%9}, {%0,%1,%2,%3};"
        : "+f"(c[0]), "+f"(c[1]), "+f"(c[2]), "+f"(c[3])
        : "r"(a[0]), "r"(a[1]), "r"(a[2]), "r"(a[3]),
          "r"(b[0]), "r"(b[1]));
}

// ================= tf32 mma.sync GEMM =================
// C[M,N] = A[M,K] @ BT[N,K]^T + bias[N].  M%128==0, N%128==0, K%32==0
// grid (N/128, M/128), block 256 = 8 warps in 2(m) x 4(n); warp tile 64x32.
#define GBK 32
#define GSTAGES 3
#define SROW 36                               // padded row stride (floats)
#define STG_FLTS (2 * 128 * SROW)             // A tile + B tile per stage
#define GSM_BYTES (GSTAGES * STG_FLTS * 4)    // 110592

__global__ __launch_bounds__(256) void gemm_tf32_mma(
    const float* __restrict__ A, const float* __restrict__ BT,
    const float* __restrict__ bias, float* __restrict__ C,
    int M, int N, int K)
{
    extern __shared__ float smf[];
    const uint32_t smb = smem_u32(smf);
    const int tid = threadIdx.x;
    const int wid = tid >> 5;
    const int lane = tid & 31;
    const int wm = wid & 1;          // 2 m-strips of 64
    const int wn = wid >> 1;         // 4 n-strips of 32
    const int bcol = blockIdx.x, brow = blockIdx.y;

    const float* Ag = A + (size_t)brow * 128 * K;
    const float* Bg = BT + (size_t)bcol * 128 * K;
    const int nkt = K / GBK;

    float acc[4][4][4];
    #pragma unroll
    for (int i = 0; i < 4; i++)
        #pragma unroll
        for (int j = 0; j < 4; j++)
            #pragma unroll
            for (int r = 0; r < 4; r++) acc[i][j][r] = 0.0f;

    // ---- stage loader: 128x32 A and B tiles, row stride SROW floats ----
    auto load_stage = [&](int buf, int k0) {
        const uint32_t sA = smb + (uint32_t)buf * STG_FLTS * 4;
        const uint32_t sB = sA + 128 * SROW * 4;
        #pragma unroll
        for (int t = 0; t < 4; t++) {
            const int i = tid + t * 256;       // 0..1023
            const int r = i >> 3;
            const int c4 = (i & 7) << 2;
            const uint32_t so = (uint32_t)(r * SROW + c4) * 4;
            cp_async16(sA + so, Ag + (size_t)r * K + k0 + c4);
            cp_async16(sB + so, Bg + (size_t)r * K + k0 + c4);
        }
        CP_COMMIT();
    };

    load_stage(0, 0);
    load_stage(1, GBK);

    const int fr = lane >> 2;    // fragment row / n-col (0..7)
    const int fc = lane & 3;     // fragment col k (0..3)

    for (int kt = 0; kt < nkt; kt++) {
        if (kt + 2 < nkt) { load_stage((kt + 2) % GSTAGES, (kt + 2) * GBK); CP_WAIT(2); }
        else if (kt + 1 < nkt) { CP_WAIT(1); }
        else { CP_WAIT(0); }
        __syncthreads();

        const int buf = kt % GSTAGES;
        const float* sA = smf + buf * STG_FLTS;
        const float* sB = sA + 128 * SROW;

        #pragma unroll
        for (int ks = 0; ks < 4; ks++) {       // 4 x K=8
            uint32_t afr[4][4], bfr[4][2];
            #pragma unroll
            for (int mt = 0; mt < 4; mt++) {
                const float* ap = sA + (wm * 64 + mt * 16 + fr) * SROW + ks * 8 + fc;
                afr[mt][0] = f2tf32(ap[0]);
                afr[mt][1] = f2tf32(ap[8 * SROW]);
                afr[mt][2] = f2tf32(ap[4]);
                afr[mt][3] = f2tf32(ap[8 * SROW + 4]);
            }
            #pragma unroll
            for (int nt = 0; nt < 4; nt++) {
                const float* bp = sB + (wn * 32 + nt * 8 + fr) * SROW + ks * 8 + fc;
                bfr[nt][0] = f2tf32(bp[0]);
                bfr[nt][1] = f2tf32(bp[4]);
            }
            #pragma unroll
            for (int mt = 0; mt < 4; mt++)
                #pragma unroll
                for (int nt = 0; nt < 4; nt++)
                    mma_tf32(acc[mt][nt], afr[mt], bfr[nt]);
        }
        __syncthreads();
    }

    // ---- epilogue: + bias, write float2 pairs ----
    #pragma unroll
    for (int mt = 0; mt < 4; mt++) {
        const size_t r0 = (size_t)brow * 128 + wm * 64 + mt * 16 + fr;
        #pragma unroll
        for (int nt = 0; nt < 4; nt++) {
            const int gc = bcol * 128 + wn * 32 + nt * 8 + fc * 2;
            const float b0 = __ldg(bias + gc);
            const float b1 = __ldg(bias + gc + 1);
            float2 o0 = make_float2(acc[mt][nt][0] + b0, acc[mt][nt][1] + b1);
            float2 o1 = make_float2(acc[mt][nt][2] + b0, acc[mt][nt][3] + b1);
            *(float2*)(C + r0 * N + gc) = o0;
            *(float2*)(C + (r0 + 8) * N + gc) = o1;
        }
    }
}

// ---------------- weight transpose: out[N,K] = in[K,N] ----------------
__global__ void transpose_kernel(const float* __restrict__ in,
                                 float* __restrict__ out, int R, int C)
{
    __shared__ float t[32][33];
    int x = blockIdx.x * 32 + threadIdx.x;
    int yb = blockIdx.y * 32;
    #pragma unroll
    for (int j = 0; j < 32; j += 8)
        t[threadIdx.y + j][threadIdx.x] = in[(size_t)(yb + threadIdx.y + j) * C + x];
    __syncthreads();
    int ox = yb + threadIdx.x;
    int oyb = blockIdx.x * 32;
    #pragma unroll
    for (int j = 0; j < 32; j += 8)
        out[(size_t)(oyb + threadIdx.y + j) * R + ox] = t[threadIdx.x][threadIdx.y + j];
}

// ---------------- Flash attention (validated in R1) ----------------
#define AQ 64
#define AK 64
#define SMS 68
#define ATTN_SMEM (4 * 64 * SMS * 4)

__global__ __launch_bounds__(256) void attn_kernel(
    const float* __restrict__ q, const float* __restrict__ kv,
    float* __restrict__ heads)
{
    const int qb = blockIdx.x;
    const int h  = blockIdx.y;
    const int b  = blockIdx.z;
    const int tid = threadIdx.x;
    const int tx = tid & 15;
    const int ty = tid >> 4;

    extern __shared__ float smf[];
    float* Qs  = smf;
    float* Kst = Qs  + 64 * SMS;
    float* Vs  = Kst + 64 * SMS;
    float* Ps  = Vs  + 64 * SMS;

    const float scale = 0.125f;

    const float* qg = q + ((size_t)b * SEQ + (size_t)qb * AQ) * DMODEL + h * HDIM;
    for (int i = tid; i < AQ * 16; i += 256) {
        const int r = i >> 4, c4 = (i & 15) * 4;
        *(float4*)&Qs[r * SMS + c4] = *(const float4*)(qg + (size_t)r * DMODEL + c4);
    }

    const float* kg = kv + (size_t)b * SEQ * KVD + h * HDIM;
    const float* vg = kg + DMODEL;

    float m[4], l[4], acc[4][4];
    #pragma unroll
    for (int i = 0; i < 4; i++) {
        m[i] = -INFINITY; l[i] = 0.0f;
        #pragma unroll
        for (int j = 0; j < 4; j++) acc[i][j] = 0.0f;
    }

    for (int k0 = 0; k0 < SEQ; k0 += AK) {
        for (int i = tid; i < AK * 16; i += 256) {
            const int kr = i >> 4, c4 = (i & 15) * 4;
            float4 kvv = *(const float4*)(kg + (size_t)(k0 + kr) * KVD + c4);
            Kst[(c4 + 0) * SMS + kr] = kvv.x;
            Kst[(c4 + 1) * SMS + kr] = kvv.y;
            Kst[(c4 + 2) * SMS + kr] = kvv.z;
            Kst[(c4 + 3) * SMS + kr] = kvv.w;
            *(float4*)&Vs[kr * SMS + c4] =
                *(const float4*)(vg + (size_t)(k0 + kr) * KVD + c4);
        }
        __syncthreads();

        float s[4][4];
        #pragma unroll
        for (int i = 0; i < 4; i++)
            #pragma unroll
            for (int j = 0; j < 4; j++) s[i][j] = 0.0f;

        #pragma unroll 8
        for (int kd = 0; kd < HDIM; kd++) {
            const float4 kc = *(const float4*)&Kst[kd * SMS + tx * 4];
            #pragma unroll
            for (int i = 0; i < 4; i++) {
                const float qv = Qs[(ty * 4 + i) * SMS + kd];
                s[i][0] = fmaf(qv, kc.x, s[i][0]);
                s[i][1] = fmaf(qv, kc.y, s[i][1]);
                s[i][2] = fmaf(qv, kc.z, s[i][2]);
                s[i][3] = fmaf(qv, kc.w, s[i][3]);
            }
        }

        float alpha[4];
        #pragma unroll
        for (int i = 0; i < 4; i++) {
            float pm = fmaxf(fmaxf(s[i][0], s[i][1]), fmaxf(s[i][2], s[i][3])) * scale;
            #pragma unroll
            for (int o = 1; o < 16; o <<= 1)
                pm = fmaxf(pm, __shfl_xor_sync(0xffffffffu, pm, o));
            const float nm = fmaxf(m[i], pm);
            alpha[i] = __expf(m[i] - nm);
            m[i] = nm;
            float ps = 0.0f;
            #pragma unroll
            for (int j = 0; j < 4; j++) {
                s[i][j] = __expf(fmaf(s[i][j], scale, -nm));
                ps += s[i][j];
            }
            #pragma unroll
            for (int o = 1; o < 16; o <<= 1)
                ps += __shfl_xor_sync(0xffffffffu, ps, o);
            l[i] = l[i] * alpha[i] + ps;
            #pragma unroll
            for (int j = 0; j < 4; j++) acc[i][j] *= alpha[i];
        }

        #pragma unroll
        for (int i = 0; i < 4; i++)
            *(float4*)&Ps[(ty * 4 + i) * SMS + tx * 4] =
                make_float4(s[i][0], s[i][1], s[i][2], s[i][3]);
        __syncthreads();

        #pragma unroll 8
        for (int kr = 0; kr < AK; kr++) {
            const float4 vv = *(const float4*)&Vs[kr * SMS + tx * 4];
            #pragma unroll
            for (int i = 0; i < 4; i++) {
                const float pv = Ps[(ty * 4 + i) * SMS + kr];
                acc[i][0] = fmaf(pv, vv.x, acc[i][0]);
                acc[i][1] = fmaf(pv, vv.y, acc[i][1]);
                acc[i][2] = fmaf(pv, vv.z, acc[i][2]);
                acc[i][3] = fmaf(pv, vv.w, acc[i][3]);
            }
        }
        __syncthreads();
    }

    float* og = heads + ((size_t)b * SEQ + (size_t)qb * AQ) * DMODEL + h * HDIM;
    #pragma unroll
    for (int i = 0; i < 4; i++) {
        const int r = ty * 4 + i;
        const float inv = 1.0f / l[i];
        *(float4*)(og + (size_t)r * DMODEL + tx * 4) =
            make_float4(acc[i][0] * inv, acc[i][1] * inv,
                        acc[i][2] * inv, acc[i][3] * inv);
    }
}

// ---------------- launch ----------------
extern "C" void kernel_launch(void* const* d_in, const int* in_sizes, int n_in,
                              void* d_out, int out_size)
{
    const float* query = (const float*)d_in[0];
    const float* value = (const float*)d_in[1];
    const float* Wq    = (const float*)d_in[2];
    const float* bq    = (const float*)d_in[3];
    const float* Wkv   = (const float*)d_in[4];
    const float* bkv   = (const float*)d_in[5];
    const float* Wo    = (const float*)d_in[6];
    const float* bo    = (const float*)d_in[7];
    float* out = (float*)d_out;

    float *gq, *gkv, *gheads, *wqT, *wkvT, *woT;
    cudaGetSymbolAddress((void**)&gq, g_q);
    cudaGetSymbolAddress((void**)&gkv, g_kv);
    cudaGetSymbolAddress((void**)&gheads, g_heads);
    cudaGetSymbolAddress((void**)&wqT, g_WqT);
    cudaGetSymbolAddress((void**)&wkvT, g_WkvT);
    cudaGetSymbolAddress((void**)&woT, g_WoT);

    const int M = BATCH * SEQ;   // 8192

    cudaFuncSetAttribute(gemm_tf32_mma, cudaFuncAttributeMaxDynamicSharedMemorySize,
                         GSM_BYTES);
    cudaFuncSetAttribute(attn_kernel, cudaFuncAttributeMaxDynamicSharedMemorySize,
                         ATTN_SMEM);

    // transpose weights: WT[N,K] = W[K,N]
    transpose_kernel<<<dim3(DMODEL / 32, DMODEL / 32), dim3(32, 8)>>>(Wq, wqT, DMODEL, DMODEL);
    transpose_kernel<<<dim3(KVD / 32, DMODEL / 32), dim3(32, 8)>>>(Wkv, wkvT, DMODEL, KVD);
    transpose_kernel<<<dim3(DMODEL / 32, DMODEL / 32), dim3(32, 8)>>>(Wo, woT, DMODEL, DMODEL);

    // q = query @ Wq + bq
    gemm_tf32_mma<<<dim3(DMODEL / 128, M / 128), 256, GSM_BYTES>>>(
        query, wqT, bq, gq, M, DMODEL, DMODEL);
    // kv = value @ Wkv + bkv
    gemm_tf32_mma<<<dim3(KVD / 128, M / 128), 256, GSM_BYTES>>>(
        value, wkvT, bkv, gkv, M, KVD, DMODEL);
    // attention
    attn_kernel<<<dim3(SEQ / AQ, NHEAD, BATCH), 256, ATTN_SMEM>>>(gq, gkv, gheads);
    // out = heads @ Wo + bo
    gemm_tf32_mma<<<dim3(DMODEL / 128, M / 128), 256, GSM_BYTES>>>(
        gheads, woT, bo, out, M, DMODEL, DMODEL);
}

// round 6
// speedup vs baseline: 5.4629x; 1.8879x over previous
#include <cuda_runtime.h>
#include <cuda_bf16.h>
#include <math.h>
#include <stdint.h>

// Problem constants
#define BATCH 8
#define SEQ   1024
#define DMODEL 1024
#define NHEAD 16
#define HDIM  64
#define KVD   2048   // 2*DMODEL

// ---------------- scratch (no cudaMalloc allowed) ----------------
__device__ float g_q[BATCH * SEQ * DMODEL];      // 32 MB
__device__ float g_kv[BATCH * SEQ * KVD];        // 64 MB
__device__ float g_heads[BATCH * SEQ * DMODEL];  // 32 MB
__device__ float g_WqT[DMODEL * DMODEL];         // 4 MB
__device__ float g_WkvT[KVD * DMODEL];           // 8 MB
__device__ float g_WoT[DMODEL * DMODEL];         // 4 MB

// ================= helpers =================
__device__ __forceinline__ uint32_t smem_u32(const void* p) {
    uint32_t a;
    asm("{ .reg .u64 t; cvta.to.shared.u64 t, %1; cvt.u32.u64 %0, t; }"
        : "=r"(a) : "l"(p));
    return a;
}

__device__ __forceinline__ void cp_async16(uint32_t dst, const void* src) {
    asm volatile("cp.async.cg.shared.global [%0], [%1], 16;"
                 :: "r"(dst), "l"(src) : "memory");
}
#define CP_COMMIT() asm volatile("cp.async.commit_group;" ::: "memory")
#define CP_WAIT(n)  asm volatile("cp.async.wait_group %0;" :: "n"(n) : "memory")

__device__ __forceinline__ uint32_t f2tf32(float x) {
    uint32_t r;
    asm("cvt.rna.tf32.f32 %0, %1;" : "=r"(r) : "f"(x));
    return r;
}
__device__ __forceinline__ float tf32f(float x) {
    return __uint_as_float(f2tf32(x));
}

// D = A(row) @ B(col) + C, tf32, m16n8k8
__device__ __forceinline__ void mma_tf32(float* c, const uint32_t* a,
                                         const uint32_t* b) {
    asm volatile(
        "mma.sync.aligned.m16n8k8.row.col.f32.tf32.tf32.f32 "
        "{%0,%1,%2,%3}, {%4,%5,%6,%7}, {%8,%9}, {%0,%1,%2,%3};"
        : "+f"(c[0]), "+f"(c[1]), "+f"(c[2]), "+f"(c[3])
        : "r"(a[0]), "r"(a[1]), "r"(a[2]), "r"(a[3]),
          "r"(b[0]), "r"(b[1]));
}

// ================= tf32 mma.sync GEMM (validated R4) =================
#define GBK 32
#define GSTAGES 3
#define SROW 36
#define STG_FLTS (2 * 128 * SROW)
#define GSM_BYTES (GSTAGES * STG_FLTS * 4)

__global__ __launch_bounds__(256) void gemm_tf32_mma(
    const float* __restrict__ A, const float* __restrict__ BT,
    const float* __restrict__ bias, float* __restrict__ C,
    int M, int N, int K)
{
    extern __shared__ float smf[];
    const uint32_t smb = smem_u32(smf);
    const int tid = threadIdx.x;
    const int wid = tid >> 5;
    const int lane = tid & 31;
    const int wm = wid & 1;
    const int wn = wid >> 1;
    const int bcol = blockIdx.x, brow = blockIdx.y;

    const float* Ag = A + (size_t)brow * 128 * K;
    const float* Bg = BT + (size_t)bcol * 128 * K;
    const int nkt = K / GBK;

    float acc[4][4][4];
    #pragma unroll
    for (int i = 0; i < 4; i++)
        #pragma unroll
        for (int j = 0; j < 4; j++)
            #pragma unroll
            for (int r = 0; r < 4; r++) acc[i][j][r] = 0.0f;

    auto load_stage = [&](int buf, int k0) {
        const uint32_t sA = smb + (uint32_t)buf * STG_FLTS * 4;
        const uint32_t sB = sA + 128 * SROW * 4;
        #pragma unroll
        for (int t = 0; t < 4; t++) {
            const int i = tid + t * 256;
            const int r = i >> 3;
            const int c4 = (i & 7) << 2;
            const uint32_t so = (uint32_t)(r * SROW + c4) * 4;
            cp_async16(sA + so, Ag + (size_t)r * K + k0 + c4);
            cp_async16(sB + so, Bg + (size_t)r * K + k0 + c4);
        }
        CP_COMMIT();
    };

    load_stage(0, 0);
    load_stage(1, GBK);

    const int fr = lane >> 2;
    const int fc = lane & 3;

    for (int kt = 0; kt < nkt; kt++) {
        if (kt + 2 < nkt) { load_stage((kt + 2) % GSTAGES, (kt + 2) * GBK); CP_WAIT(2); }
        else if (kt + 1 < nkt) { CP_WAIT(1); }
        else { CP_WAIT(0); }
        __syncthreads();

        const int buf = kt % GSTAGES;
        const float* sA = smf + buf * STG_FLTS;
        const float* sB = sA + 128 * SROW;

        #pragma unroll
        for (int ks = 0; ks < 4; ks++) {
            uint32_t afr[4][4], bfr[4][2];
            #pragma unroll
            for (int mt = 0; mt < 4; mt++) {
                const float* ap = sA + (wm * 64 + mt * 16 + fr) * SROW + ks * 8 + fc;
                afr[mt][0] = f2tf32(ap[0]);
                afr[mt][1] = f2tf32(ap[8 * SROW]);
                afr[mt][2] = f2tf32(ap[4]);
                afr[mt][3] = f2tf32(ap[8 * SROW + 4]);
            }
            #pragma unroll
            for (int nt = 0; nt < 4; nt++) {
                const float* bp = sB + (wn * 32 + nt * 8 + fr) * SROW + ks * 8 + fc;
                bfr[nt][0] = f2tf32(bp[0]);
                bfr[nt][1] = f2tf32(bp[4]);
            }
            #pragma unroll
            for (int mt = 0; mt < 4; mt++)
                #pragma unroll
                for (int nt = 0; nt < 4; nt++)
                    mma_tf32(acc[mt][nt], afr[mt], bfr[nt]);
        }
        __syncthreads();
    }

    #pragma unroll
    for (int mt = 0; mt < 4; mt++) {
        const size_t r0 = (size_t)brow * 128 + wm * 64 + mt * 16 + fr;
        #pragma unroll
        for (int nt = 0; nt < 4; nt++) {
            const int gc = bcol * 128 + wn * 32 + nt * 8 + fc * 2;
            const float b0 = __ldg(bias + gc);
            const float b1 = __ldg(bias + gc + 1);
            float2 o0 = make_float2(acc[mt][nt][0] + b0, acc[mt][nt][1] + b1);
            float2 o1 = make_float2(acc[mt][nt][2] + b0, acc[mt][nt][3] + b1);
            *(float2*)(C + r0 * N + gc) = o0;
            *(float2*)(C + (r0 + 8) * N + gc) = o1;
        }
    }
}

// ---------------- weight transpose: out[N,K] = in[K,N] ----------------
__global__ void transpose_kernel(const float* __restrict__ in,
                                 float* __restrict__ out, int R, int C)
{
    __shared__ float t[32][33];
    int x = blockIdx.x * 32 + threadIdx.x;
    int yb = blockIdx.y * 32;
    #pragma unroll
    for (int j = 0; j < 32; j += 8)
        t[threadIdx.y + j][threadIdx.x] = in[(size_t)(yb + threadIdx.y + j) * C + x];
    __syncthreads();
    int ox = yb + threadIdx.x;
    int oyb = blockIdx.x * 32;
    #pragma unroll
    for (int j = 0; j < 32; j += 8)
        out[(size_t)(oyb + threadIdx.y + j) * R + ox] = t[threadIdx.x][threadIdx.y + j];
}

// ================= Flash attention with tf32 mma.sync =================
// grid (SEQ/128, NHEAD, BATCH), block 256 = 8 warps, warp owns 16 q-rows.
// Key tiles of 64. Smem strides chosen for conflict-free fragment loads.
#define QST 68
#define KST 68
#define VST 72
#define PST 68
#define SMQ 0
#define SMK (128 * QST)                 // 8704
#define SMV (SMK + 64 * KST)            // 13056
#define SMP (SMV + 64 * VST)            // 17664
#define ATTN_SMEM ((SMP + 8 * 16 * PST) * 4)   // 105472 B

__global__ __launch_bounds__(256, 2) void attn_mma(
    const float* __restrict__ q, const float* __restrict__ kv,
    float* __restrict__ heads)
{
    const int qb = blockIdx.x;
    const int h  = blockIdx.y;
    const int b  = blockIdx.z;
    const int tid = threadIdx.x;
    const int wid = tid >> 5;
    const int lane = tid & 31;
    const int fr = lane >> 2;    // group id (0..7)
    const int fc = lane & 3;     // thread-in-group (0..3)

    extern __shared__ float smf[];
    float* Qs = smf + SMQ;                    // [128][QST] tf32-rounded
    float* Ks = smf + SMK;                    // [64][KST]  key-major
    float* Vs = smf + SMV;                    // [64][VST]  key-major
    float* Pw = smf + SMP + wid * 16 * PST;   // per-warp [16][PST]

    const float scale = 0.125f;

    // ---- load Q tile (128 x 64), tf32-rounded ----
    const float* qg = q + ((size_t)b * SEQ + (size_t)qb * 128) * DMODEL + h * HDIM;
    #pragma unroll
    for (int t = 0; t < 8; t++) {
        const int i = tid + t * 256;          // 0..2047
        const int r = i >> 4, c4 = (i & 15) * 4;
        float4 v = *(const float4*)(qg + (size_t)r * DMODEL + c4);
        *(float4*)&Qs[r * QST + c4] =
            make_float4(tf32f(v.x), tf32f(v.y), tf32f(v.z), tf32f(v.w));
    }

    const float* kg = kv + (size_t)b * SEQ * KVD + h * HDIM;
    const float* vg = kg + DMODEL;

    float m0 = -INFINITY, m1 = -INFINITY, l0 = 0.0f, l1 = 0.0f;
    float acc[8][4];
    #pragma unroll
    for (int nt = 0; nt < 8; nt++)
        #pragma unroll
        for (int j = 0; j < 4; j++) acc[nt][j] = 0.0f;

    for (int kt = 0; kt < 16; kt++) {
        if (kt) __syncthreads();     // prior reads of Ks/Vs done
        const int k0 = kt * 64;
        #pragma unroll
        for (int t = 0; t < 4; t++) {
            const int i = tid + t * 256;      // 0..1023
            const int r = i >> 4, c4 = (i & 15) * 4;
            float4 kk = *(const float4*)(kg + (size_t)(k0 + r) * KVD + c4);
            float4 vv = *(const float4*)(vg + (size_t)(k0 + r) * KVD + c4);
            *(float4*)&Ks[r * KST + c4] =
                make_float4(tf32f(kk.x), tf32f(kk.y), tf32f(kk.z), tf32f(kk.w));
            *(float4*)&Vs[r * VST + c4] =
                make_float4(tf32f(vv.x), tf32f(vv.y), tf32f(vv.z), tf32f(vv.w));
        }
        __syncthreads();

        // ---- S = Q @ K^T : warp computes 16x64 ----
        float s[8][4];
        #pragma unroll
        for (int nt = 0; nt < 8; nt++)
            #pragma unroll
            for (int j = 0; j < 4; j++) s[nt][j] = 0.0f;

        #pragma unroll
        for (int ks = 0; ks < 8; ks++) {
            uint32_t a[4];
            const float* qp = Qs + (wid * 16 + fr) * QST + ks * 8 + fc;
            a[0] = __float_as_uint(qp[0]);
            a[1] = __float_as_uint(qp[8 * QST]);
            a[2] = __float_as_uint(qp[4]);
            a[3] = __float_as_uint(qp[8 * QST + 4]);
            #pragma unroll
            for (int nt = 0; nt < 8; nt++) {
                const float* kp = Ks + (nt * 8 + fr) * KST + ks * 8 + fc;
                uint32_t bf[2] = { __float_as_uint(kp[0]), __float_as_uint(kp[4]) };
                mma_tf32(s[nt], a, bf);
            }
        }

        // ---- online softmax (rows fr and fr+8 of warp strip) ----
        float mx0 = s[0][0], mx1 = s[0][2];
        #pragma unroll
        for (int nt = 0; nt < 8; nt++) {
            mx0 = fmaxf(mx0, fmaxf(s[nt][0], s[nt][1]));
            mx1 = fmaxf(mx1, fmaxf(s[nt][2], s[nt][3]));
        }
        mx0 *= scale; mx1 *= scale;
        mx0 = fmaxf(mx0, __shfl_xor_sync(0xffffffffu, mx0, 1));
        mx0 = fmaxf(mx0, __shfl_xor_sync(0xffffffffu, mx0, 2));
        mx1 = fmaxf(mx1, __shfl_xor_sync(0xffffffffu, mx1, 1));
        mx1 = fmaxf(mx1, __shfl_xor_sync(0xffffffffu, mx1, 2));

        const float nm0 = fmaxf(m0, mx0);
        const float nm1 = fmaxf(m1, mx1);
        const float al0 = __expf(m0 - nm0);
        const float al1 = __expf(m1 - nm1);
        m0 = nm0; m1 = nm1;

        float sum0 = 0.0f, sum1 = 0.0f;
        #pragma unroll
        for (int nt = 0; nt < 8; nt++) {
            s[nt][0] = __expf(fmaf(s[nt][0], scale, -nm0)); sum0 += s[nt][0];
            s[nt][1] = __expf(fmaf(s[nt][1], scale, -nm0)); sum0 += s[nt][1];
            s[nt][2] = __expf(fmaf(s[nt][2], scale, -nm1)); sum1 += s[nt][2];
            s[nt][3] = __expf(fmaf(s[nt][3], scale, -nm1)); sum1 += s[nt][3];
        }
        sum0 += __shfl_xor_sync(0xffffffffu, sum0, 1);
        sum0 += __shfl_xor_sync(0xffffffffu, sum0, 2);
        sum1 += __shfl_xor_sync(0xffffffffu, sum1, 1);
        sum1 += __shfl_xor_sync(0xffffffffu, sum1, 2);
        l0 = l0 * al0 + sum0;
        l1 = l1 * al1 + sum1;

        #pragma unroll
        for (int nt = 0; nt < 8; nt++) {
            acc[nt][0] *= al0; acc[nt][1] *= al0;
            acc[nt][2] *= al1; acc[nt][3] *= al1;
        }

        // ---- stage P (tf32-rounded) to per-warp smem ----
        #pragma unroll
        for (int nt = 0; nt < 8; nt++) {
            *(float2*)(Pw + fr * PST + nt * 8 + fc * 2) =
                make_float2(tf32f(s[nt][0]), tf32f(s[nt][1]));
            *(float2*)(Pw + (fr + 8) * PST + nt * 8 + fc * 2) =
                make_float2(tf32f(s[nt][2]), tf32f(s[nt][3]));
        }
        __syncwarp();

        // ---- acc += P @ V ----
        #pragma unroll
        for (int kk = 0; kk < 8; kk++) {
            uint32_t a[4];
            const float* pp = Pw + fr * PST + kk * 8 + fc;
            a[0] = __float_as_uint(pp[0]);
            a[1] = __float_as_uint(pp[8 * PST]);
            a[2] = __float_as_uint(pp[4]);
            a[3] = __float_as_uint(pp[8 * PST + 4]);
            #pragma unroll
            for (int nt = 0; nt < 8; nt++) {
                const float* vp = Vs + (kk * 8 + fc) * VST + nt * 8 + fr;
                uint32_t bf[2] = { __float_as_uint(vp[0]),
                                   __float_as_uint(vp[4 * VST]) };
                mma_tf32(acc[nt], a, bf);
            }
        }
        __syncwarp();
    }

    // ---- epilogue ----
    const float inv0 = 1.0f / l0;
    const float inv1 = 1.0f / l1;
    const int r0 = qb * 128 + wid * 16 + fr;
    float* og = heads + ((size_t)b * SEQ + r0) * DMODEL + h * HDIM;
    #pragma unroll
    for (int nt = 0; nt < 8; nt++) {
        *(float2*)(og + nt * 8 + fc * 2) =
            make_float2(acc[nt][0] * inv0, acc[nt][1] * inv0);
        *(float2*)(og + 8 * DMODEL + nt * 8 + fc * 2) =
            make_float2(acc[nt][2] * inv1, acc[nt][3] * inv1);
    }
}

// ---------------- launch ----------------
extern "C" void kernel_launch(void* const* d_in, const int* in_sizes, int n_in,
                              void* d_out, int out_size)
{
    const float* query = (const float*)d_in[0];
    const float* value = (const float*)d_in[1];
    const float* Wq    = (const float*)d_in[2];
    const float* bq    = (const float*)d_in[3];
    const float* Wkv   = (const float*)d_in[4];
    const float* bkv   = (const float*)d_in[5];
    const float* Wo    = (const float*)d_in[6];
    const float* bo    = (const float*)d_in[7];
    float* out = (float*)d_out;

    float *gq, *gkv, *gheads, *wqT, *wkvT, *woT;
    cudaGetSymbolAddress((void**)&gq, g_q);
    cudaGetSymbolAddress((void**)&gkv, g_kv);
    cudaGetSymbolAddress((void**)&gheads, g_heads);
    cudaGetSymbolAddress((void**)&wqT, g_WqT);
    cudaGetSymbolAddress((void**)&wkvT, g_WkvT);
    cudaGetSymbolAddress((void**)&woT, g_WoT);

    const int M = BATCH * SEQ;   // 8192

    cudaFuncSetAttribute(gemm_tf32_mma, cudaFuncAttributeMaxDynamicSharedMemorySize,
                         GSM_BYTES);
    cudaFuncSetAttribute(attn_mma, cudaFuncAttributeMaxDynamicSharedMemorySize,
                         ATTN_SMEM);

    // transpose weights: WT[N,K] = W[K,N]
    transpose_kernel<<<dim3(DMODEL / 32, DMODEL / 32), dim3(32, 8)>>>(Wq, wqT, DMODEL, DMODEL);
    transpose_kernel<<<dim3(KVD / 32, DMODEL / 32), dim3(32, 8)>>>(Wkv, wkvT, DMODEL, KVD);
    transpose_kernel<<<dim3(DMODEL / 32, DMODEL / 32), dim3(32, 8)>>>(Wo, woT, DMODEL, DMODEL);

    // q = query @ Wq + bq
    gemm_tf32_mma<<<dim3(DMODEL / 128, M / 128), 256, GSM_BYTES>>>(
        query, wqT, bq, gq, M, DMODEL, DMODEL);
    // kv = value @ Wkv + bkv
    gemm_tf32_mma<<<dim3(KVD / 128, M / 128), 256, GSM_BYTES>>>(
        value, wkvT, bkv, gkv, M, KVD, DMODEL);
    // attention (tensor-core flash)
    attn_mma<<<dim3(SEQ / 128, NHEAD, BATCH), 256, ATTN_SMEM>>>(gq, gkv, gheads);
    // out = heads @ Wo + bo
    gemm_tf32_mma<<<dim3(DMODEL / 128, M / 128), 256, GSM_BYTES>>>(
        gheads, woT, bo, out, M, DMODEL, DMODEL);
}